// round 13
// baseline (speedup 1.0000x reference)
#include <cuda_runtime.h>
#include <cstdint>

#define BB 16
#define NN 256
#define CC 4096
#define FINF 1e30f
#define RCACHE 216   // rows of the cost matrix cached in SMEM (216KB)

// Scratch (static device globals — no allocation allowed)
__device__ float g_rowmax[BB * NN];
__device__ float g_rowsum[BB * NN];
__device__ float g_cost[(size_t)BB * NN * NN];

// ---------------------------------------------------------------------------
// Kernel A: per-(b,n) online max + sum of exp over C=4096 logits
// ---------------------------------------------------------------------------
__global__ void k_lse(const float* __restrict__ logits) {
    int row = blockIdx.x;                    // b*NN + n
    const float* x = logits + (size_t)row * CC;
    float m = -FINF, s = 0.f;
    for (int c = threadIdx.x; c < CC; c += 256) {
        float v = x[c];
        if (v > m) { s = s * __expf(m - v) + 1.f; m = v; }
        else       { s += __expf(v - m); }
    }
    __shared__ float sm[256], ss[256];
    sm[threadIdx.x] = m; ss[threadIdx.x] = s;
    __syncthreads();
    for (int off = 128; off; off >>= 1) {
        if (threadIdx.x < off) {
            float m1 = sm[threadIdx.x], s1 = ss[threadIdx.x];
            float m2 = sm[threadIdx.x + off], s2 = ss[threadIdx.x + off];
            float M = fmaxf(m1, m2);
            sm[threadIdx.x] = M;
            ss[threadIdx.x] = s1 * __expf(m1 - M) + s2 * __expf(m2 - M);
        }
        __syncthreads();
    }
    if (threadIdx.x == 0) { g_rowmax[row] = sm[0]; g_rowsum[row] = ss[0]; }
}

// ---------------------------------------------------------------------------
// Kernel B: cost[b][n][m] = -softmax(logits[b,n])[label[b,m]] + 5*L1(p,g)
// ---------------------------------------------------------------------------
__global__ void k_cost(const float* __restrict__ pred_ctrl,
                       const float* __restrict__ logits,
                       const float* __restrict__ gt_ctrl,
                       const void*  __restrict__ labels_raw,
                       float* __restrict__ out_C) {
    int n = blockIdx.x, b = blockIdx.y, m = threadIdx.x;
    int row = b * NN + n;

    __shared__ float p[8];
    __shared__ float s_mx, s_sum;
    __shared__ int s_use64;
    if (m < 8) p[m] = pred_ctrl[(size_t)row * 8 + m];
    if (m == 0) {
        s_mx = g_rowmax[row];
        s_sum = g_rowsum[row];
        const long long* L = (const long long*)labels_raw;
        int ok = 1;
        #pragma unroll
        for (int t = 0; t < 8; t++) {
            long long v = L[t];
            if (v < 0 || v >= CC) ok = 0;
        }
        s_use64 = ok;
    }
    __syncthreads();

    int lbl;
    if (s_use64) lbl = (int)((const long long*)labels_raw)[b * NN + m];
    else         lbl = ((const int*)labels_raw)[b * NN + m];

    float l = logits[(size_t)row * CC + lbl];
    float prob = __expf(l - s_mx) / s_sum;

    const float* g = gt_ctrl + ((size_t)b * NN + m) * 8;
    float bez = 0.f;
    #pragma unroll
    for (int k = 0; k < 8; k++) bez += fabsf(p[k] - g[k]);

    float cst = -prob + 5.0f * bez;
    size_t idx = (size_t)row * NN + m;
    g_cost[idx] = cst;
    out_C[idx] = cst;
}

// order-preserving float->u32 map (bijective; exact)
__device__ __forceinline__ unsigned f2ord(float f) {
    unsigned b = __float_as_uint(f);
    return (b & 0x80000000u) ? ~b : (b | 0x80000000u);
}
__device__ __forceinline__ float ord2f(unsigned o) {
    unsigned b = (o & 0x80000000u) ? (o & 0x7fffffffu) : ~o;
    return __uint_as_float(b);
}

// ---------------------------------------------------------------------------
// Kernel C: full Jonker–Volgenant LSA: column reduction + greedy assign +
// 2-pass augmenting row reduction + shortest-augmenting-path for leftovers.
// One warp per batch. First RCACHE cost rows cached in dynamic SMEM.
// SAP inner loop: register state, tree-reduced local argmin (depth 3),
// two REDUX.MIN.U32 for exact warp argmin with lowest-j tie-break.
// ---------------------------------------------------------------------------
__global__ void k_lsa(float* __restrict__ out_rows, float* __restrict__ out_cols) {
    extern __shared__ float srows[];            // RCACHE * NN floats
    __shared__ float u_sh[NN], spc_sh[NN];
    __shared__ int path_sh[NN], row4col[NN], col4row[NN];
    __shared__ int freelist[NN];
    __shared__ int nfree_sh;
    __shared__ unsigned char sr_sh[NN];

    int b = blockIdx.x;
    int lane = threadIdx.x;
    const float* cost = g_cost + (size_t)b * NN * NN;

    // Preload cached rows into SMEM (vectorized, coalesced)
    {
        const float4* src = (const float4*)cost;
        float4* dst = (float4*)srows;
        for (int t = lane; t < RCACHE * NN / 4; t += 32) dst[t] = src[t];
    }

    for (int r = lane; r < NN; r += 32) {
        u_sh[r] = 0.f; row4col[r] = -1; col4row[r] = -1; sr_sh[r] = 0;
    }
    __syncwarp();

    // ---- Phase 1: column reduction  v[j] = min_i cost[i][j] ----
    float v_reg[8];
    int amin_reg[8];
    {
        #pragma unroll
        for (int q = 0; q < 8; q++) { v_reg[q] = FINF; amin_reg[q] = 0; }
        for (int i = 0; i < RCACHE; i++) {
            const float* cr = srows + i * NN;
            #pragma unroll
            for (int q = 0; q < 8; q++) {
                float c = cr[lane + 32 * q];
                if (c < v_reg[q]) { v_reg[q] = c; amin_reg[q] = i; }
            }
        }
        for (int i = RCACHE; i < NN; i++) {
            const float* cr = cost + (size_t)i * NN;
            #pragma unroll
            for (int q = 0; q < 8; q++) {
                float c = __ldg(cr + lane + 32 * q);
                if (c < v_reg[q]) { v_reg[q] = c; amin_reg[q] = i; }
            }
        }
    }

    // greedy assignment on zero-reduced edges
    #pragma unroll
    for (int q = 0; q < 8; q++) {
        int j = lane + 32 * q;
        int istar = amin_reg[q];
        if (atomicCAS(&col4row[istar], -1, j) == -1) row4col[j] = istar;
    }
    __syncwarp();

    // build free-row list (deterministic order)
    if (lane == 0) nfree_sh = 0;
    __syncwarp();
    for (int base = 0; base < NN; base += 32) {
        unsigned mfree = __ballot_sync(0xffffffffu, col4row[base + lane] < 0);
        if (lane == 0) {
            while (mfree) { int t = __ffs(mfree) - 1; freelist[nfree_sh++] = base + t; mfree &= mfree - 1; }
        }
        __syncwarp();
    }

    // ---- Phase 2: augmenting row reduction (2 passes) ----
    for (int pass = 0; pass < 2; pass++) {
        int nf = nfree_sh;
        if (nf == 0) break;
        if (lane == 0) nfree_sh = 0;
        __syncwarp();
        for (int t = 0; t < nf; t++) {
            int i = freelist[t];
            float cv[8];
            if (i < RCACHE) {
                const float* cr = srows + i * NN;
                #pragma unroll
                for (int q = 0; q < 8; q++) cv[q] = cr[lane + 32 * q];
            } else {
                const float* cr = cost + (size_t)i * NN;
                #pragma unroll
                for (int q = 0; q < 8; q++) cv[q] = __ldg(cr + lane + 32 * q);
            }
            float m1 = FINF, m2 = FINF; int j1 = -1;
            #pragma unroll
            for (int q = 0; q < 8; q++) {
                float r = cv[q] - v_reg[q];
                if (r < m1) { m2 = m1; m1 = r; j1 = lane + 32 * q; }
                else if (r < m2) { m2 = r; }
            }
            #pragma unroll
            for (int off = 16; off; off >>= 1) {
                float om1 = __shfl_xor_sync(0xffffffffu, m1, off);
                int   oj1 = __shfl_xor_sync(0xffffffffu, j1, off);
                float om2 = __shfl_xor_sync(0xffffffffu, m2, off);
                if (om1 < m1) { m2 = fminf(om2, m1); m1 = om1; j1 = oj1; }
                else          { m2 = fminf(m2, om1); }
            }
            m1 = __shfl_sync(0xffffffffu, m1, 0);
            j1 = __shfl_sync(0xffffffffu, j1, 0);
            m2 = __shfl_sync(0xffffffffu, m2, 0);

            float delta = m2 - m1;                       // >= 0
            if (lane == (j1 & 31)) v_reg[j1 >> 5] -= delta;
            if (lane == 0) {
                u_sh[i] = m2;
                int k = row4col[j1];
                row4col[j1] = i; col4row[i] = j1;
                if (k >= 0) { col4row[k] = -1; freelist[nfree_sh++] = k; }
            }
            __syncwarp();
        }
    }

    // ---- Phase 3: shortest augmenting path for remaining free rows ----
    float spc_reg[8];
    int path_reg[8];
    unsigned scbits;

    for (int cur = 0; cur < NN; cur++) {
        if (col4row[cur] >= 0) continue;

        scbits = 0u;
        #pragma unroll
        for (int q = 0; q < 8; q++) { spc_reg[q] = FINF; path_reg[q] = -1; }
        for (int r = lane; r < NN; r += 32) sr_sh[r] = 0;
        __syncwarp();

        int i = cur;
        float minVal = 0.f;
        int sink = -1;

        while (true) {
            if (lane == 0) sr_sh[i] = 1;
            float base = minVal - u_sh[i];

            float cv[8];
            if (i < RCACHE) {
                const float* cr = srows + i * NN;
                #pragma unroll
                for (int q = 0; q < 8; q++) cv[q] = cr[lane + 32 * q];
            } else {
                const float* cr = cost + (size_t)i * NN;
                #pragma unroll
                for (int q = 0; q < 8; q++) cv[q] = __ldg(cr + lane + 32 * q);
            }

            // relax (independent per q) + collect candidates
            float cand[8]; int cj[8];
            #pragma unroll
            for (int q = 0; q < 8; q++) {
                float r = (base + cv[q]) - v_reg[q];
                bool sc = (scbits >> q) & 1u;
                bool upd = !sc && (r < spc_reg[q]);
                spc_reg[q]  = upd ? r : spc_reg[q];
                path_reg[q] = upd ? i : path_reg[q];
                cand[q] = sc ? FINF : spc_reg[q];
                cj[q] = lane + 32 * q;
            }
            // depth-3 tree argmin (strict < keeps lower q => lower j on ties)
            if (cand[1] < cand[0]) { cand[0] = cand[1]; cj[0] = cj[1]; }
            if (cand[3] < cand[2]) { cand[2] = cand[3]; cj[2] = cj[3]; }
            if (cand[5] < cand[4]) { cand[4] = cand[5]; cj[4] = cj[5]; }
            if (cand[7] < cand[6]) { cand[6] = cand[7]; cj[6] = cj[7]; }
            if (cand[2] < cand[0]) { cand[0] = cand[2]; cj[0] = cj[2]; }
            if (cand[6] < cand[4]) { cand[4] = cand[6]; cj[4] = cj[6]; }
            if (cand[4] < cand[0]) { cand[0] = cand[4]; cj[0] = cj[4]; }

            // exact warp argmin: value (order-preserving bits), lowest-j tie-break
            unsigned bestbits = f2ord(cand[0]);
            unsigned vmin = __reduce_min_sync(0xffffffffu, bestbits);
            unsigned jc = (bestbits == vmin) ? (unsigned)cj[0] : 0xffffffffu;
            unsigned j = __reduce_min_sync(0xffffffffu, jc);
            minVal = ord2f(vmin);

            if (lane == (j & 31u)) scbits |= 1u << (j >> 5);
            int r4c = row4col[j];
            if (r4c < 0) { sink = (int)j; break; }
            i = r4c;
        }
        __syncwarp();

        // dump distributed spc & path to shared (once per search)
        #pragma unroll
        for (int q = 0; q < 8; q++) {
            spc_sh[lane + 32 * q] = spc_reg[q];
            path_sh[lane + 32 * q] = path_reg[q];
        }
        __syncwarp();

        if (lane == 0) u_sh[cur] += minVal;
        __syncwarp();
        for (int r = lane; r < NN; r += 32) {
            if (sr_sh[r] && r != cur) {
                int jj = col4row[r];
                jj = jj < 0 ? 0 : jj;
                u_sh[r] = (u_sh[r] + minVal) - spc_sh[jj];
            }
        }
        #pragma unroll
        for (int q = 0; q < 8; q++)
            if ((scbits >> q) & 1u) v_reg[q] -= (minVal - spc_reg[q]);
        __syncwarp();

        if (lane == 0) {
            int j = sink;
            for (int guard = 0; guard < NN; guard++) {
                int i2 = path_sh[j];
                if (i2 < 0) break;
                row4col[j] = i2;
                int jn = col4row[i2];
                col4row[i2] = j;
                j = jn;
                if (i2 == cur) break;
            }
        }
        __syncwarp();
    }

    for (int r = lane; r < NN; r += 32) {
        out_rows[b * NN + r] = (float)r;
        out_cols[b * NN + r] = (float)col4row[r];
    }
}

// ---------------------------------------------------------------------------
extern "C" void kernel_launch(void* const* d_in, const int* in_sizes, int n_in,
                              void* d_out, int out_size) {
    const float* pred_ctrl   = (const float*)d_in[0];  // (16,256,4,2)
    const float* pred_logits = (const float*)d_in[1];  // (16,256,4096)
    const float* gt_ctrl     = (const float*)d_in[2];  // (16,256,4,2)
    const void*  gt_labels   = d_in[3];                // (16,256) int32/int64

    float* out = (float*)d_out;
    float* out_rows = out;                 // 4096
    float* out_cols = out + BB * NN;       // 4096
    float* out_C    = out + 2 * BB * NN;   // 1048576

    const int smem_dyn = RCACHE * NN * sizeof(float);  // 221184 bytes
    cudaFuncSetAttribute(k_lsa, cudaFuncAttributeMaxDynamicSharedMemorySize, smem_dyn);

    k_lse<<<BB * NN, 256>>>(pred_logits);
    dim3 gridB(NN, BB);
    k_cost<<<gridB, NN>>>(pred_ctrl, pred_logits, gt_ctrl, gt_labels, out_C);
    k_lsa<<<BB, 32, smem_dyn>>>(out_rows, out_cols);
}

// round 15
// speedup vs baseline: 1.1510x; 1.1510x over previous
#include <cuda_runtime.h>
#include <cstdint>

#define BB 16
#define NN 256
#define CC 4096
#define FINF 1e30f
#define RCACHE 216   // rows of the cost matrix cached in SMEM (216KB)

// Scratch (static device globals — no allocation allowed)
__device__ float g_cost[(size_t)BB * NN * NN];

// ---------------------------------------------------------------------------
// Fused kernel: per (b,n) row — softmax LSE over C=4096, then all 256 costs.
// cost[b][n][m] = -softmax(logits[b,n])[label[b,m]] + 5*L1(p,g)
// ---------------------------------------------------------------------------
__global__ void k_cost_fused(const float* __restrict__ pred_ctrl,
                             const float* __restrict__ logits,
                             const float* __restrict__ gt_ctrl,
                             const void*  __restrict__ labels_raw,
                             float* __restrict__ out_C) {
    int row = blockIdx.x;                    // b*NN + n
    int b = row >> 8;
    int m = threadIdx.x;
    const float* x = logits + (size_t)row * CC;

    // Phase A: online max + sum of exp over C
    float mx = -FINF, s = 0.f;
    for (int c = m; c < CC; c += 256) {
        float v = x[c];
        if (v > mx) { s = s * __expf(mx - v) + 1.f; mx = v; }
        else        { s += __expf(v - mx); }
    }
    __shared__ float sm[256], ss[256];
    sm[m] = mx; ss[m] = s;
    __syncthreads();
    for (int off = 128; off; off >>= 1) {
        if (m < off) {
            float m1 = sm[m], s1 = ss[m];
            float m2 = sm[m + off], s2 = ss[m + off];
            float M = fmaxf(m1, m2);
            sm[m] = M;
            ss[m] = s1 * __expf(m1 - M) + s2 * __expf(m2 - M);
        }
        __syncthreads();
    }

    // Phase B: costs
    __shared__ float p[8];
    __shared__ int s_use64;
    if (m < 8) p[m] = pred_ctrl[(size_t)row * 8 + m];
    if (m == 0) {
        const long long* L = (const long long*)labels_raw;
        int ok = 1;
        #pragma unroll
        for (int t = 0; t < 8; t++) {
            long long v = L[t];
            if (v < 0 || v >= CC) ok = 0;
        }
        s_use64 = ok;
    }
    __syncthreads();

    float s_mx = sm[0], s_sum = ss[0];

    int lbl;
    if (s_use64) lbl = (int)((const long long*)labels_raw)[b * NN + m];
    else         lbl = ((const int*)labels_raw)[b * NN + m];

    float l = x[lbl];
    float prob = __expf(l - s_mx) / s_sum;

    const float* g = gt_ctrl + ((size_t)b * NN + m) * 8;
    float bez = 0.f;
    #pragma unroll
    for (int k = 0; k < 8; k++) bez += fabsf(p[k] - g[k]);

    float cst = -prob + 5.0f * bez;
    size_t idx = (size_t)row * NN + m;
    g_cost[idx] = cst;
    out_C[idx] = cst;
}

// order-preserving float->u32 map (bijective; exact)
__device__ __forceinline__ unsigned f2ord(float f) {
    unsigned b = __float_as_uint(f);
    return (b & 0x80000000u) ? ~b : (b | 0x80000000u);
}
__device__ __forceinline__ float ord2f(unsigned o) {
    unsigned b = (o & 0x80000000u) ? (o & 0x7fffffffu) : ~o;
    return __uint_as_float(b);
}

// ---------------------------------------------------------------------------
// Kernel C: full Jonker–Volgenant LSA: column reduction + greedy assign +
// 3-pass augmenting row reduction + shortest-augmenting-path for leftovers.
// One warp per batch. First RCACHE cost rows cached in dynamic SMEM.
// SAP inner loop: register state (spc, path), linear-chain local argmin,
// two REDUX.MIN.U32 for exact warp argmin with lowest-j tie-break.
// ---------------------------------------------------------------------------
__global__ void k_lsa(float* __restrict__ out_rows, float* __restrict__ out_cols) {
    extern __shared__ float srows[];            // RCACHE * NN floats
    __shared__ float u_sh[NN], spc_sh[NN];
    __shared__ int path_sh[NN], row4col[NN], col4row[NN];
    __shared__ int freelist[NN];
    __shared__ int nfree_sh;
    __shared__ unsigned char sr_sh[NN];

    int b = blockIdx.x;
    int lane = threadIdx.x;
    const float* cost = g_cost + (size_t)b * NN * NN;

    // Preload cached rows into SMEM (vectorized, coalesced)
    {
        const float4* src = (const float4*)cost;
        float4* dst = (float4*)srows;
        for (int t = lane; t < RCACHE * NN / 4; t += 32) dst[t] = src[t];
    }

    for (int r = lane; r < NN; r += 32) {
        u_sh[r] = 0.f; row4col[r] = -1; col4row[r] = -1; sr_sh[r] = 0;
    }
    __syncwarp();

    // ---- Phase 1: column reduction  v[j] = min_i cost[i][j] ----
    float v_reg[8];
    int amin_reg[8];
    {
        #pragma unroll
        for (int q = 0; q < 8; q++) { v_reg[q] = FINF; amin_reg[q] = 0; }
        for (int i = 0; i < RCACHE; i++) {
            const float* cr = srows + i * NN;
            #pragma unroll
            for (int q = 0; q < 8; q++) {
                float c = cr[lane + 32 * q];
                if (c < v_reg[q]) { v_reg[q] = c; amin_reg[q] = i; }
            }
        }
        for (int i = RCACHE; i < NN; i++) {
            const float* cr = cost + (size_t)i * NN;
            #pragma unroll
            for (int q = 0; q < 8; q++) {
                float c = __ldg(cr + lane + 32 * q);
                if (c < v_reg[q]) { v_reg[q] = c; amin_reg[q] = i; }
            }
        }
    }

    // greedy assignment on zero-reduced edges
    #pragma unroll
    for (int q = 0; q < 8; q++) {
        int j = lane + 32 * q;
        int istar = amin_reg[q];
        if (atomicCAS(&col4row[istar], -1, j) == -1) row4col[j] = istar;
    }
    __syncwarp();

    // build free-row list (deterministic order)
    if (lane == 0) nfree_sh = 0;
    __syncwarp();
    for (int base = 0; base < NN; base += 32) {
        unsigned mfree = __ballot_sync(0xffffffffu, col4row[base + lane] < 0);
        if (lane == 0) {
            while (mfree) { int t = __ffs(mfree) - 1; freelist[nfree_sh++] = base + t; mfree &= mfree - 1; }
        }
        __syncwarp();
    }

    // ---- Phase 2: augmenting row reduction (3 passes) ----
    for (int pass = 0; pass < 3; pass++) {
        int nf = nfree_sh;
        if (nf == 0) break;
        if (lane == 0) nfree_sh = 0;
        __syncwarp();
        for (int t = 0; t < nf; t++) {
            int i = freelist[t];
            float cv[8];
            if (i < RCACHE) {
                const float* cr = srows + i * NN;
                #pragma unroll
                for (int q = 0; q < 8; q++) cv[q] = cr[lane + 32 * q];
            } else {
                const float* cr = cost + (size_t)i * NN;
                #pragma unroll
                for (int q = 0; q < 8; q++) cv[q] = __ldg(cr + lane + 32 * q);
            }
            float m1 = FINF, m2 = FINF; int j1 = -1;
            #pragma unroll
            for (int q = 0; q < 8; q++) {
                float r = cv[q] - v_reg[q];
                if (r < m1) { m2 = m1; m1 = r; j1 = lane + 32 * q; }
                else if (r < m2) { m2 = r; }
            }
            #pragma unroll
            for (int off = 16; off; off >>= 1) {
                float om1 = __shfl_xor_sync(0xffffffffu, m1, off);
                int   oj1 = __shfl_xor_sync(0xffffffffu, j1, off);
                float om2 = __shfl_xor_sync(0xffffffffu, m2, off);
                if (om1 < m1) { m2 = fminf(om2, m1); m1 = om1; j1 = oj1; }
                else          { m2 = fminf(m2, om1); }
            }
            m1 = __shfl_sync(0xffffffffu, m1, 0);
            j1 = __shfl_sync(0xffffffffu, j1, 0);
            m2 = __shfl_sync(0xffffffffu, m2, 0);

            float delta = m2 - m1;                       // >= 0
            if (lane == (j1 & 31)) v_reg[j1 >> 5] -= delta;
            if (lane == 0) {
                u_sh[i] = m2;
                int k = row4col[j1];
                row4col[j1] = i; col4row[i] = j1;
                if (k >= 0) { col4row[k] = -1; freelist[nfree_sh++] = k; }
            }
            __syncwarp();
        }
    }

    // ---- Phase 3: shortest augmenting path for remaining free rows ----
    float spc_reg[8];
    int path_reg[8];
    unsigned scbits;

    for (int cur = 0; cur < NN; cur++) {
        if (col4row[cur] >= 0) continue;

        scbits = 0u;
        #pragma unroll
        for (int q = 0; q < 8; q++) { spc_reg[q] = FINF; path_reg[q] = -1; }
        for (int r = lane; r < NN; r += 32) sr_sh[r] = 0;
        __syncwarp();

        int i = cur;
        float minVal = 0.f;
        int sink = -1;

        while (true) {
            if (lane == 0) sr_sh[i] = 1;
            float base = minVal - u_sh[i];

            float cv[8];
            if (i < RCACHE) {
                const float* cr = srows + i * NN;
                #pragma unroll
                for (int q = 0; q < 8; q++) cv[q] = cr[lane + 32 * q];
            } else {
                const float* cr = cost + (size_t)i * NN;
                #pragma unroll
                for (int q = 0; q < 8; q++) cv[q] = __ldg(cr + lane + 32 * q);
            }

            // local argmin over q in float domain; first-win => lowest j in lane
            float bestv = FINF; int bestq = 0;
            #pragma unroll
            for (int q = 0; q < 8; q++) {
                float r = (base + cv[q]) - v_reg[q];
                bool sc = (scbits >> q) & 1u;
                bool upd = !sc && (r < spc_reg[q]);
                spc_reg[q]  = upd ? r : spc_reg[q];
                path_reg[q] = upd ? i : path_reg[q];
                float cand = sc ? FINF : spc_reg[q];
                bool bt = cand < bestv;
                bestv = bt ? cand : bestv;
                bestq = bt ? q : bestq;
            }
            // exact warp argmin: value (order-preserving bits), lowest-j tie-break
            unsigned bestbits = f2ord(bestv);
            unsigned vmin = __reduce_min_sync(0xffffffffu, bestbits);
            unsigned jc = (bestbits == vmin) ? (unsigned)(lane + 32 * bestq) : 0xffffffffu;
            unsigned j = __reduce_min_sync(0xffffffffu, jc);
            minVal = ord2f(vmin);

            if (lane == (j & 31u)) scbits |= 1u << (j >> 5);
            int r4c = row4col[j];
            if (r4c < 0) { sink = (int)j; break; }
            i = r4c;
        }
        __syncwarp();

        // dump distributed spc & path to shared (once per search)
        #pragma unroll
        for (int q = 0; q < 8; q++) {
            spc_sh[lane + 32 * q] = spc_reg[q];
            path_sh[lane + 32 * q] = path_reg[q];
        }
        __syncwarp();

        if (lane == 0) u_sh[cur] += minVal;
        __syncwarp();
        for (int r = lane; r < NN; r += 32) {
            if (sr_sh[r] && r != cur) {
                int jj = col4row[r];
                jj = jj < 0 ? 0 : jj;
                u_sh[r] = (u_sh[r] + minVal) - spc_sh[jj];
            }
        }
        #pragma unroll
        for (int q = 0; q < 8; q++)
            if ((scbits >> q) & 1u) v_reg[q] -= (minVal - spc_reg[q]);
        __syncwarp();

        if (lane == 0) {
            int j = sink;
            for (int guard = 0; guard < NN; guard++) {
                int i2 = path_sh[j];
                if (i2 < 0) break;
                row4col[j] = i2;
                int jn = col4row[i2];
                col4row[i2] = j;
                j = jn;
                if (i2 == cur) break;
            }
        }
        __syncwarp();
    }

    for (int r = lane; r < NN; r += 32) {
        out_rows[b * NN + r] = (float)r;
        out_cols[b * NN + r] = (float)col4row[r];
    }
}

// ---------------------------------------------------------------------------
extern "C" void kernel_launch(void* const* d_in, const int* in_sizes, int n_in,
                              void* d_out, int out_size) {
    const float* pred_ctrl   = (const float*)d_in[0];  // (16,256,4,2)
    const float* pred_logits = (const float*)d_in[1];  // (16,256,4096)
    const float* gt_ctrl     = (const float*)d_in[2];  // (16,256,4,2)
    const void*  gt_labels   = d_in[3];                // (16,256) int32/int64

    float* out = (float*)d_out;
    float* out_rows = out;                 // 4096
    float* out_cols = out + BB * NN;       // 4096
    float* out_C    = out + 2 * BB * NN;   // 1048576

    const int smem_dyn = RCACHE * NN * sizeof(float);  // 221184 bytes
    cudaFuncSetAttribute(k_lsa, cudaFuncAttributeMaxDynamicSharedMemorySize, smem_dyn);

    k_cost_fused<<<BB * NN, 256>>>(pred_ctrl, pred_logits, gt_ctrl, gt_labels, out_C);
    k_lsa<<<BB, 32, smem_dyn>>>(out_rows, out_cols);
}